// round 1
// baseline (speedup 1.0000x reference)
#include <cuda_runtime.h>

#define Nn 100000
#define Rr 3
#define Ee 320000
#define HDIM 128

// ---------------- scratch (device globals; no allocation allowed) ----------------
__device__ float g_A[Rr * 128 * 128];     // Wt_src @ Wg  (per relation)
__device__ float g_B[Rr * 128 * 128];     // Wt_dst @ Wg
__device__ float g_bA[Rr * 128];          // bt_src @ Wg
__device__ float g_bB[Rr * 128];          // bt_dst @ Wg
__device__ float g_Qt[Rr * 4 * 128];      // er projection, layout [r][h][f]
__device__ float g_qb[Rr * 4];
__device__ float g_hs[Rr * Nn * HDIM];    // projected src features (with bias)
__device__ float g_el[Rr * Nn * 4];
__device__ float g_er[Rr * Nn * 4];
__device__ float g_e[Rr * Ee * 4];        // per-edge e, then ex
__device__ int   g_m[Rr * Nn * 4];        // encoded segment max
__device__ float g_ssum[Rr * Nn * 4];
__device__ float g_rst[Rr * Nn * HDIM];   // aggregation -> z_r (in place)
__device__ float g_tmp[Rr * Nn * HDIM];   // z_r @ W1 + b1
__device__ float g_wsum[Rr];
__device__ float g_a[Rr];

// order-preserving float<->int encoding for atomicMax
__device__ __forceinline__ int enc_f(float f) {
    int i = __float_as_int(f);
    return (i >= 0) ? i : (i ^ 0x7FFFFFFF);
}
__device__ __forceinline__ float dec_f(int i) {
    return __int_as_float((i >= 0) ? i : (i ^ 0x7FFFFFFF));
}
__device__ __forceinline__ float lrelu(float x) { return x > 0.f ? x : 0.2f * x; }

// ---------------- K0: composed weights ----------------
__global__ void k_compose(const float* __restrict__ Wt_dst, const float* __restrict__ bt_dst,
                          const float* __restrict__ Wt_src, const float* __restrict__ bt_src,
                          const float* __restrict__ Wg)
{
    int r = blockIdx.y;
    int o = blockIdx.x * 256 + threadIdx.x;
    if (o >= 2 * 16384 + 2 * 128) return;
    const float* WgR = Wg + r * 16384;
    if (o < 32768) {
        int which = o >> 14;
        int idx = o & 16383;
        int f = idx >> 7, j = idx & 127;
        const float* row = which ? (Wt_dst + f * 128) : (Wt_src + r * 16384 + f * 128);
        float s = 0.f;
        #pragma unroll 8
        for (int k = 0; k < 128; k++) s += row[k] * WgR[k * 128 + j];
        if (which) g_B[r * 16384 + idx] = s;
        else       g_A[r * 16384 + idx] = s;
    } else {
        int o2 = o - 32768;
        int which = o2 >> 7;
        int j = o2 & 127;
        const float* bv = which ? bt_dst : (bt_src + r * 128);
        float s = 0.f;
        #pragma unroll 8
        for (int k = 0; k < 128; k++) s += bv[k] * WgR[k * 128 + j];
        if (which) g_bB[r * 128 + j] = s;
        else       g_bA[r * 128 + j] = s;
    }
}

// ---------------- K0b: er projection Q = B . attn_r ----------------
__global__ void k_attnproj(const float* __restrict__ attn_r_)
{
    int r = blockIdx.x;
    int f = threadIdx.x; // 0..127
    #pragma unroll
    for (int h = 0; h < 4; h++) {
        float s = 0.f;
        #pragma unroll 8
        for (int d = 0; d < 32; d++)
            s += g_B[r * 16384 + f * 128 + h * 32 + d] * attn_r_[r * 128 + h * 32 + d];
        g_Qt[r * 512 + h * 128 + f] = s;
    }
    if (f < 4) {
        int h = f;
        float s = 0.f;
        for (int d = 0; d < 32; d++)
            s += g_bB[r * 128 + h * 32 + d] * attn_r_[r * 128 + h * 32 + d];
        g_qb[r * 4 + h] = s;
    }
}

// ---------------- init (per launch: graph-replay safe) ----------------
__global__ void k_init()
{
    int i = blockIdx.x * 256 + threadIdx.x;           // float4 index
    if (i < Rr * Nn * 32) *(float4*)&g_rst[i * 4] = make_float4(0.f, 0.f, 0.f, 0.f);
    if (i < Rr * Nn) {
        *(int4*)&g_m[i * 4] = make_int4((int)0x80000000, (int)0x80000000, (int)0x80000000, (int)0x80000000);
        *(float4*)&g_ssum[i * 4] = make_float4(0.f, 0.f, 0.f, 0.f);
    }
    if (i < Rr) g_wsum[i] = 0.f;
}

// ---------------- tiled fp32 GEMM: O = X @ W + bias, per-relation strides ----------------
__global__ __launch_bounds__(256)
void k_gemm(const float* __restrict__ Xb, int xs,
            const float* __restrict__ Wb, int ws,
            const float* __restrict__ bb, int bs,
            float* __restrict__ Ob, int os, int nrows)
{
    const int r = blockIdx.z;
    const float* X = Xb + (long)r * xs;
    const float* W = Wb + (long)r * ws;
    const float* bias = bb + (long)r * bs;
    float* O = Ob + (long)r * os;

    __shared__ float As[32][68];   // [k][m], padded for float4-aligned reads
    __shared__ float Bs[32][128];  // [k][n]

    const int t = threadIdx.x;
    const int tx = t & 15, ty = t >> 4;
    const int row0 = blockIdx.x * 64;

    float acc[4][8];
    #pragma unroll
    for (int i = 0; i < 4; i++)
        #pragma unroll
        for (int j = 0; j < 8; j++) acc[i][j] = 0.f;

    for (int k0 = 0; k0 < 128; k0 += 32) {
        #pragma unroll
        for (int i = 0; i < 8; i++) {
            int idx = t + i * 256;
            int m = idx >> 5, k = idx & 31;
            int row = row0 + m;
            As[k][m] = (row < nrows) ? X[(long)row * 128 + k0 + k] : 0.f;
        }
        #pragma unroll
        for (int i = 0; i < 4; i++) {
            int idx = t + i * 256;      // float4 index among 1024
            int k = idx >> 5, n4 = idx & 31;
            *(float4*)&Bs[k][n4 * 4] = *(const float4*)&W[(long)(k0 + k) * 128 + n4 * 4];
        }
        __syncthreads();
        #pragma unroll
        for (int k = 0; k < 32; k++) {
            float4 a4 = *(const float4*)&As[k][ty * 4];
            float4 b0 = *(const float4*)&Bs[k][tx * 8];
            float4 b1 = *(const float4*)&Bs[k][tx * 8 + 4];
            float aa[4] = {a4.x, a4.y, a4.z, a4.w};
            float bbv[8] = {b0.x, b0.y, b0.z, b0.w, b1.x, b1.y, b1.z, b1.w};
            #pragma unroll
            for (int i = 0; i < 4; i++)
                #pragma unroll
                for (int j = 0; j < 8; j++)
                    acc[i][j] += aa[i] * bbv[j];
        }
        __syncthreads();
    }
    float4 bv0 = *(const float4*)&bias[tx * 8];
    float4 bv1 = *(const float4*)&bias[tx * 8 + 4];
    #pragma unroll
    for (int i = 0; i < 4; i++) {
        int row = row0 + ty * 4 + i;
        if (row < nrows) {
            float4 o0 = make_float4(acc[i][0] + bv0.x, acc[i][1] + bv0.y,
                                    acc[i][2] + bv0.z, acc[i][3] + bv0.w);
            float4 o1 = make_float4(acc[i][4] + bv1.x, acc[i][5] + bv1.y,
                                    acc[i][6] + bv1.z, acc[i][7] + bv1.w);
            *(float4*)&O[(long)row * 128 + tx * 8] = o0;
            *(float4*)&O[(long)row * 128 + tx * 8 + 4] = o1;
        }
    }
}

// ---------------- el = hs . attn_l (warp per (r,n)) ----------------
__global__ void k_el(const float* __restrict__ attn_l_)
{
    int w = (blockIdx.x * 256 + threadIdx.x) >> 5;
    int lane = threadIdx.x & 31;
    if (w >= Rr * Nn) return;
    int r = w / Nn, n = w % Nn;
    float4 hv = *(const float4*)&g_hs[((long)r * Nn + n) * 128 + lane * 4];
    float4 av = *(const float4*)&attn_l_[r * 128 + lane * 4];
    float s = hv.x * av.x + hv.y * av.y + hv.z * av.z + hv.w * av.w;
    s += __shfl_down_sync(0xffffffffu, s, 4, 8);
    s += __shfl_down_sync(0xffffffffu, s, 2, 8);
    s += __shfl_down_sync(0xffffffffu, s, 1, 8);
    if ((lane & 7) == 0) g_el[((long)r * Nn + n) * 4 + (lane >> 3)] = s;
}

// ---------------- er = dst_feat @ Q + qb (warp per n, all 3 relations) ----------------
__global__ void k_er(const float* __restrict__ dst_feat)
{
    __shared__ float sQ[Rr * 512];
    __shared__ float sqb[12];
    int t = threadIdx.x;
    for (int i = t; i < Rr * 512; i += 256) sQ[i] = g_Qt[i];
    if (t < 12) sqb[t] = g_qb[t];
    __syncthreads();
    int wid = t >> 5, lane = t & 31;
    int n = blockIdx.x * 8 + wid;
    if (n >= Nn) return;
    float4 x = *(const float4*)&dst_feat[(long)n * 128 + lane * 4];
    float p[12];
    #pragma unroll
    for (int i = 0; i < 12; i++) {
        float4 q = *(const float4*)&sQ[i * 128 + lane * 4];   // i = r*4+h
        p[i] = x.x * q.x + x.y * q.y + x.z * q.z + x.w * q.w;
    }
    #pragma unroll
    for (int i = 0; i < 12; i++)
        #pragma unroll
        for (int off = 16; off; off >>= 1)
            p[i] += __shfl_down_sync(0xffffffffu, p[i], off);
    if (lane == 0) {
        #pragma unroll
        for (int i = 0; i < 12; i++) {
            int r = i >> 2, h = i & 3;
            g_er[((long)r * Nn + n) * 4 + h] = p[i] + sqb[i];
        }
    }
}

// ---------------- edge pass 1: e = lrelu(el[s]+er[d]); segment max ----------------
__global__ void k_edge1(const int* __restrict__ sidx, const int* __restrict__ didx)
{
    int i = blockIdx.x * 256 + threadIdx.x;
    if (i >= Rr * Ee) return;
    int r = i / Ee;
    int s = sidx[i], d = didx[i];
    float4 el = *(const float4*)&g_el[((long)r * Nn + s) * 4];
    float4 er = *(const float4*)&g_er[((long)r * Nn + d) * 4];
    float4 e;
    e.x = lrelu(el.x + er.x);
    e.y = lrelu(el.y + er.y);
    e.z = lrelu(el.z + er.z);
    e.w = lrelu(el.w + er.w);
    *(float4*)&g_e[(long)i * 4] = e;
    int* mp = &g_m[((long)r * Nn + d) * 4];
    atomicMax(mp + 0, enc_f(e.x));
    atomicMax(mp + 1, enc_f(e.y));
    atomicMax(mp + 2, enc_f(e.z));
    atomicMax(mp + 3, enc_f(e.w));
}

// ---------------- edge pass 2: ex = exp(e - m[d]); segment sum ----------------
__global__ void k_edge2(const int* __restrict__ sidx, const int* __restrict__ didx)
{
    int i = blockIdx.x * 256 + threadIdx.x;
    if (i >= Rr * Ee) return;
    int r = i / Ee;
    int d = didx[i];
    float4 e = *(const float4*)&g_e[(long)i * 4];
    int4 mv = *(const int4*)&g_m[((long)r * Nn + d) * 4];
    float4 ex;
    ex.x = expf(e.x - dec_f(mv.x));
    ex.y = expf(e.y - dec_f(mv.y));
    ex.z = expf(e.z - dec_f(mv.z));
    ex.w = expf(e.w - dec_f(mv.w));
    *(float4*)&g_e[(long)i * 4] = ex;
    float* sp = &g_ssum[((long)r * Nn + d) * 4];
    atomicAdd(sp + 0, ex.x);
    atomicAdd(sp + 1, ex.y);
    atomicAdd(sp + 2, ex.z);
    atomicAdd(sp + 3, ex.w);
}

// ---------------- edge pass 3: rst[d] += alpha * hs[s]  (warp per edge) ----------------
__global__ void k_edge3(const int* __restrict__ sidx, const int* __restrict__ didx)
{
    int w = (blockIdx.x * 256 + threadIdx.x) >> 5;
    int lane = threadIdx.x & 31;
    if (w >= Rr * Ee) return;
    int r = w / Ee;
    int s = sidx[w], d = didx[w];
    int h = lane >> 3;
    float ex = g_e[(long)w * 4 + h];
    float ss = g_ssum[((long)r * Nn + d) * 4 + h];
    float alpha = ex / (ss + 1e-9f);
    float4 hv = *(const float4*)&g_hs[((long)r * Nn + s) * 128 + lane * 4];
    float vx = hv.x * alpha, vy = hv.y * alpha, vz = hv.z * alpha, vw = hv.w * alpha;
    float* dst = &g_rst[((long)r * Nn + d) * 128 + lane * 4];
    asm volatile("red.global.add.v4.f32 [%0], {%1,%2,%3,%4};"
                 :: "l"(dst), "f"(vx), "f"(vy), "f"(vz), "f"(vw) : "memory");
}

// ---------------- z_r = elu(rst + bias_g), in place ----------------
__global__ void k_elu(const float* __restrict__ bias_g)
{
    int i = blockIdx.x * 256 + threadIdx.x;    // float4 index over Rr*Nn*32
    if (i >= Rr * Nn * 32) return;
    int j4 = i & 31;
    int r = i / (Nn * 32);
    float4 b = *(const float4*)&bias_g[r * 128 + j4 * 4];
    float4 v = *(float4*)&g_rst[(long)i * 4];
    v.x += b.x; v.y += b.y; v.z += b.z; v.w += b.w;
    v.x = v.x > 0.f ? v.x : expm1f(v.x);
    v.y = v.y > 0.f ? v.y : expm1f(v.y);
    v.z = v.z > 0.f ? v.z : expm1f(v.z);
    v.w = v.w > 0.f ? v.w : expm1f(v.w);
    *(float4*)&g_rst[(long)i * 4] = v;
}

// ---------------- semantic: wsum[r] += sum_n tanh(tmp[n]) . W2 ----------------
__global__ void k_wred(const float* __restrict__ W2)
{
    __shared__ float sred[8];
    int r = blockIdx.y;
    int t = threadIdx.x, wid = t >> 5, lane = t & 31;
    float4 w2 = *(const float4*)&W2[lane * 4];
    float acc = 0.f;
    int base = blockIdx.x * 64 + wid * 8;
    #pragma unroll
    for (int i = 0; i < 8; i++) {
        int n = base + i;
        if (n < Nn) {
            float4 v = *(const float4*)&g_tmp[((long)r * Nn + n) * 128 + lane * 4];
            acc += tanhf(v.x) * w2.x + tanhf(v.y) * w2.y + tanhf(v.z) * w2.z + tanhf(v.w) * w2.w;
        }
    }
    #pragma unroll
    for (int off = 16; off; off >>= 1) acc += __shfl_down_sync(0xffffffffu, acc, off);
    if (lane == 0) sred[wid] = acc;
    __syncthreads();
    if (t == 0) {
        float s = 0.f;
        #pragma unroll
        for (int i = 0; i < 8; i++) s += sred[i];
        atomicAdd(&g_wsum[r], s);
    }
}

// ---------------- softmax over relations, write att_mp ----------------
__global__ void k_soft(float* __restrict__ out)
{
    if (threadIdx.x == 0) {
        float v0 = g_wsum[0] / (float)Nn, v1 = g_wsum[1] / (float)Nn, v2 = g_wsum[2] / (float)Nn;
        float m = fmaxf(v0, fmaxf(v1, v2));
        float e0 = expf(v0 - m), e1 = expf(v1 - m), e2 = expf(v2 - m);
        float s = e0 + e1 + e2;
        g_a[0] = e0 / s; g_a[1] = e1 / s; g_a[2] = e2 / s;
        out[(long)Nn * 128 + 0] = e0 / s;
        out[(long)Nn * 128 + 1] = e1 / s;
        out[(long)Nn * 128 + 2] = e2 / s;
    }
}

// ---------------- z = sum_r a[r] * z_r ----------------
__global__ void k_final(float* __restrict__ out)
{
    int i = blockIdx.x * 256 + threadIdx.x;   // float4 index over Nn*32
    if (i >= Nn * 32) return;
    float a0 = g_a[0], a1 = g_a[1], a2 = g_a[2];
    float4 v0 = *(const float4*)&g_rst[(long)i * 4];
    float4 v1 = *(const float4*)&g_rst[((long)Nn * 32 + i) * 4];
    float4 v2 = *(const float4*)&g_rst[((long)2 * Nn * 32 + i) * 4];
    float4 z;
    z.x = a0 * v0.x + a1 * v1.x + a2 * v2.x;
    z.y = a0 * v0.y + a1 * v1.y + a2 * v2.y;
    z.z = a0 * v0.z + a1 * v1.z + a2 * v2.z;
    z.w = a0 * v0.w + a1 * v1.w + a2 * v2.w;
    *(float4*)&out[(long)i * 4] = z;
}

// ---------------- launch ----------------
extern "C" void kernel_launch(void* const* d_in, const int* in_sizes, int n_in,
                              void* d_out, int out_size)
{
    const float* dst_feat  = (const float*)d_in[0];
    const float* src_feats = (const float*)d_in[1];
    const int*   src_idx   = (const int*)d_in[2];
    const int*   dst_idx   = (const int*)d_in[3];
    const float* Wt_dst    = (const float*)d_in[4];
    const float* bt_dst    = (const float*)d_in[5];
    const float* Wt_src    = (const float*)d_in[6];
    const float* bt_src    = (const float*)d_in[7];
    const float* Wg        = (const float*)d_in[8];
    const float* attn_l    = (const float*)d_in[9];
    const float* attn_r    = (const float*)d_in[10];
    const float* bias_g    = (const float*)d_in[11];
    const float* W1        = (const float*)d_in[12];
    const float* b1        = (const float*)d_in[13];
    const float* W2        = (const float*)d_in[14];
    float* out = (float*)d_out;

    void *pA, *pbA, *phs, *prst, *ptmp;
    cudaGetSymbolAddress(&pA,   g_A);
    cudaGetSymbolAddress(&pbA,  g_bA);
    cudaGetSymbolAddress(&phs,  g_hs);
    cudaGetSymbolAddress(&prst, g_rst);
    cudaGetSymbolAddress(&ptmp, g_tmp);

    k_compose<<<dim3(129, Rr), 256>>>(Wt_dst, bt_dst, Wt_src, bt_src, Wg);
    k_attnproj<<<Rr, 128>>>(attn_r);
    k_init<<<(Rr * Nn * 32 + 255) / 256, 256>>>();

    // hs[r] = src_feats[r] @ A[r] + bA[r]
    k_gemm<<<dim3((Nn + 63) / 64, 1, Rr), 256>>>(
        src_feats, Nn * 128, (const float*)pA, 16384,
        (const float*)pbA, 128, (float*)phs, Nn * 128, Nn);

    k_el<<<(Rr * Nn + 7) / 8, 256>>>(attn_l);
    k_er<<<(Nn + 7) / 8, 256>>>(dst_feat);

    k_edge1<<<(Rr * Ee + 255) / 256, 256>>>(src_idx, dst_idx);
    k_edge2<<<(Rr * Ee + 255) / 256, 256>>>(src_idx, dst_idx);
    k_edge3<<<(Rr * Ee + 7) / 8, 256>>>(src_idx, dst_idx);

    k_elu<<<(Rr * Nn * 32 + 255) / 256, 256>>>(bias_g);

    // tmp[r] = z_r @ W1 + b1
    k_gemm<<<dim3((Nn + 63) / 64, 1, Rr), 256>>>(
        (const float*)prst, Nn * 128, W1, 0,
        b1, 0, (float*)ptmp, Nn * 128, Nn);

    k_wred<<<dim3((Nn + 63) / 64, Rr), 256>>>(W2);
    k_soft<<<1, 32>>>(out);
    k_final<<<(Nn * 32 + 255) / 256, 256>>>(out);
}

// round 7
// speedup vs baseline: 1.3054x; 1.3054x over previous
#include <cuda_runtime.h>
#include <cuda_bf16.h>
#include <mma.h>
#include <cstdint>

using namespace nvcuda;

#define Nn 100000
#define Rr 3
#define Ee 320000
#define HDIM 128

// ---------------- scratch (device globals) ----------------
__device__ float g_B[Rr * 128 * 128];               // Wt_dst @ Wg (fp32, for attnproj)
__device__ float g_bA[Rr * 128];                    // bt_src @ Wg
__device__ float g_bB[Rr * 128];                    // bt_dst @ Wg
__device__ float g_Qt[Rr * 4 * 128];                // er projection [r][h][f]
__device__ float g_qb[Rr * 4];
__device__ __nv_bfloat16 g_Whi[Rr * 128 * 128];     // (Wt_src@Wg)^T bf16 hi  [n][k]
__device__ __nv_bfloat16 g_Wlo[Rr * 128 * 128];     // lo
__device__ __nv_bfloat16 g_W1hi[128 * 128];         // W1^T bf16 hi [n][k]
__device__ __nv_bfloat16 g_W1lo[128 * 128];
__device__ float g_hs[Rr * Nn * HDIM];              // projected src features (biased)
__device__ float g_el[Rr * Nn * 4];
__device__ float g_er[Rr * Nn * 4];
__device__ float g_e[Rr * Ee * 4];                  // ex per edge
__device__ float g_ssum[Rr * Nn * 4];
__device__ float g_rst[Rr * Nn * HDIM];             // raw aggregation (pre bias/elu)
__device__ float g_wsum[Rr];
__device__ float g_a[Rr];

__device__ __forceinline__ float lrelu(float x) { return x > 0.f ? x : 0.2f * x; }

__device__ __forceinline__ uint32_t smem_u32(const void* p) {
    uint32_t a;
    asm("{ .reg .u64 t; cvta.to.shared.u64 t, %1; cvt.u32.u64 %0, t; }" : "=r"(a) : "l"(p));
    return a;
}
__device__ __forceinline__ void cp16(uint32_t dst, const void* src) {
    asm volatile("cp.async.cg.shared.global [%0], [%1], 16;" :: "r"(dst), "l"(src) : "memory");
}
__device__ __forceinline__ void cp_commit() {
    asm volatile("cp.async.commit_group;" ::: "memory");
}
__device__ __forceinline__ void cp_wait() {
    asm volatile("cp.async.wait_group 0;" ::: "memory");
}

// ---------------- SMEM overlay for GEMM kernels ----------------
#define LDA 136   // bf16 elements per A/B smem row (8.5*16B -> conflict-free ldmatrix)
#define LDC 132   // f32 elements per C smem row
struct SmemG {
    __nv_bfloat16 Ahi[128 * LDA];
    __nv_bfloat16 Alo[128 * LDA];
    __nv_bfloat16 Bh[128 * LDA];
    __nv_bfloat16 Bl[128 * LDA];
    float C[128 * LDC];
    float v0[128], v1[128], v2[128];
    float red[8];
};
#define SM_TOTAL ((int)sizeof(SmemG))

// split fp32 -> hi/lo bf16 pair, store 4 values (8B each) to A tiles
__device__ __forceinline__ void split_store4(SmemG* s, int row, int c4, float4 v) {
    __nv_bfloat16 h0 = __float2bfloat16(v.x), h1 = __float2bfloat16(v.y);
    __nv_bfloat16 h2 = __float2bfloat16(v.z), h3 = __float2bfloat16(v.w);
    __nv_bfloat16 l0 = __float2bfloat16(v.x - __bfloat162float(h0));
    __nv_bfloat16 l1 = __float2bfloat16(v.y - __bfloat162float(h1));
    __nv_bfloat16 l2 = __float2bfloat16(v.z - __bfloat162float(h2));
    __nv_bfloat16 l3 = __float2bfloat16(v.w - __bfloat162float(h3));
    __nv_bfloat162 hA = __halves2bfloat162(h0, h1), hB = __halves2bfloat162(h2, h3);
    __nv_bfloat162 lA = __halves2bfloat162(l0, l1), lB = __halves2bfloat162(l2, l3);
    int off = row * LDA + c4 * 4;
    *(uint2*)&s->Ahi[off] = make_uint2(*(uint32_t*)&hA, *(uint32_t*)&hB);
    *(uint2*)&s->Alo[off] = make_uint2(*(uint32_t*)&lA, *(uint32_t*)&lB);
}

// issue async loads for the 128x128 weight tile (hi+lo)
// 2048 chunks of 8 bf16: 128 rows (n) x 16 k-chunks (k8)
__device__ __forceinline__ void load_B_async(SmemG* s, const __nv_bfloat16* Bhi,
                                             const __nv_bfloat16* Blo, int t) {
    uint32_t bh = smem_u32(s->Bh), bl = smem_u32(s->Bl);
    #pragma unroll
    for (int i = 0; i < 8; i++) {
        int e = i * 256 + t;
        int n = e >> 4, k8 = e & 15;          // FIX: was >>3 / &7 (OOB + half-filled tile)
        uint32_t so = (uint32_t)(n * LDA + k8 * 8) * 2;
        cp16(bh + so, Bhi + (size_t)n * 128 + k8 * 8);
        cp16(bl + so, Blo + (size_t)n * 128 + k8 * 8);
    }
    cp_commit();
}

// the 3-pass split-bf16 MMA mainloop; leaves C staged in smem
__device__ __forceinline__ void mma_main(SmemG* s, int t) {
    int w = t >> 5;
    int row0w = w * 16;
    wmma::fragment<wmma::accumulator, 16, 16, 16, float> acc[8];
    #pragma unroll
    for (int n = 0; n < 8; n++) wmma::fill_fragment(acc[n], 0.f);

    #pragma unroll
    for (int pass = 0; pass < 3; pass++) {
        const __nv_bfloat16* As = (pass == 2) ? s->Alo : s->Ahi;
        const __nv_bfloat16* Bs = (pass == 1) ? s->Bl : s->Bh;
        #pragma unroll
        for (int k = 0; k < 8; k++) {
            wmma::fragment<wmma::matrix_a, 16, 16, 16, __nv_bfloat16, wmma::row_major> af;
            wmma::load_matrix_sync(af, As + row0w * LDA + k * 16, LDA);
            #pragma unroll
            for (int n = 0; n < 8; n++) {
                wmma::fragment<wmma::matrix_b, 16, 16, 16, __nv_bfloat16, wmma::col_major> bf;
                wmma::load_matrix_sync(bf, Bs + n * 16 * LDA + k * 16, LDA);
                wmma::mma_sync(acc[n], af, bf, acc[n]);
            }
        }
    }
    #pragma unroll
    for (int n = 0; n < 8; n++)
        wmma::store_matrix_sync(s->C + row0w * LDC + n * 16, acc[n], LDC, wmma::mem_row_major);
}

// ---------------- K0: composed weights ----------------
__global__ void k_compose(const float* __restrict__ Wt_dst, const float* __restrict__ bt_dst,
                          const float* __restrict__ Wt_src, const float* __restrict__ bt_src,
                          const float* __restrict__ Wg)
{
    int r = blockIdx.y;
    int o = blockIdx.x * 256 + threadIdx.x;
    if (o >= 2 * 16384 + 2 * 128) return;
    const float* WgR = Wg + r * 16384;
    if (o < 32768) {
        int which = o >> 14;
        int idx = o & 16383;
        int f = idx >> 7, j = idx & 127;
        const float* row = which ? (Wt_dst + f * 128) : (Wt_src + r * 16384 + f * 128);
        float s = 0.f;
        #pragma unroll 8
        for (int k = 0; k < 128; k++) s += row[k] * WgR[k * 128 + j];
        if (which) {
            g_B[r * 16384 + idx] = s;
        } else {
            __nv_bfloat16 h = __float2bfloat16(s);
            __nv_bfloat16 l = __float2bfloat16(s - __bfloat162float(h));
            g_Whi[r * 16384 + j * 128 + f] = h;   // transposed [n=j][k=f]
            g_Wlo[r * 16384 + j * 128 + f] = l;
        }
    } else {
        int o2 = o - 32768;
        int which = o2 >> 7;
        int j = o2 & 127;
        const float* bv = which ? bt_dst : (bt_src + r * 128);
        float s = 0.f;
        #pragma unroll 8
        for (int k = 0; k < 128; k++) s += bv[k] * WgR[k * 128 + j];
        if (which) g_bB[r * 128 + j] = s;
        else       g_bA[r * 128 + j] = s;
    }
}

// ---------------- K0b: W1^T bf16 split ----------------
__global__ void k_prepW1(const float* __restrict__ W1)
{
    int idx = blockIdx.x * 256 + threadIdx.x;
    if (idx >= 16384) return;
    int n = idx >> 7, k = idx & 127;
    float w = W1[k * 128 + n];
    __nv_bfloat16 h = __float2bfloat16(w);
    __nv_bfloat16 l = __float2bfloat16(w - __bfloat162float(h));
    g_W1hi[n * 128 + k] = h;
    g_W1lo[n * 128 + k] = l;
}

// ---------------- K0c: er projection Q = B . attn_r ----------------
__global__ void k_attnproj(const float* __restrict__ attn_r_)
{
    int r = blockIdx.x;
    int f = threadIdx.x;
    #pragma unroll
    for (int h = 0; h < 4; h++) {
        float s = 0.f;
        #pragma unroll 8
        for (int d = 0; d < 32; d++)
            s += g_B[r * 16384 + f * 128 + h * 32 + d] * attn_r_[r * 128 + h * 32 + d];
        g_Qt[r * 512 + h * 128 + f] = s;
    }
    if (f < 4) {
        int h = f;
        float s = 0.f;
        for (int d = 0; d < 32; d++)
            s += g_bB[r * 128 + h * 32 + d] * attn_r_[r * 128 + h * 32 + d];
        g_qb[r * 4 + h] = s;
    }
}

// ---------------- init ----------------
__global__ void k_init()
{
    int i = blockIdx.x * 256 + threadIdx.x;
    if (i < Rr * Nn * 32) *(float4*)&g_rst[i * 4] = make_float4(0.f, 0.f, 0.f, 0.f);
    if (i < Rr * Nn) *(float4*)&g_ssum[i * 4] = make_float4(0.f, 0.f, 0.f, 0.f);
    if (i < Rr) g_wsum[i] = 0.f;
}

// ---------------- GEMM1 (wmma): hs = X @ A + bA, fused el ----------------
__global__ __launch_bounds__(256)
void k_gemm1_tc(const float* __restrict__ src_feats, const float* __restrict__ attn_l_)
{
    extern __shared__ char smraw[];
    SmemG* s = (SmemG*)smraw;
    int t = threadIdx.x;
    int r = blockIdx.y;
    int row0 = blockIdx.x * 128;

    if (t < 128) {
        s->v0[t] = g_bA[r * 128 + t];
        s->v1[t] = attn_l_[r * 128 + t];
    }
    load_B_async(s, g_Whi + r * 16384, g_Wlo + r * 16384, t);

    const float* X = src_feats + (size_t)r * Nn * 128;
    #pragma unroll
    for (int i = 0; i < 16; i++) {
        int e = i * 256 + t;
        int row = e >> 5, c4 = e & 31;
        int g = row0 + row;
        float4 v = (g < Nn) ? *(const float4*)&X[(size_t)g * 128 + c4 * 4]
                            : make_float4(0.f, 0.f, 0.f, 0.f);
        split_store4(s, row, c4, v);
    }
    cp_wait();
    __syncthreads();

    mma_main(s, t);
    __syncthreads();

    // epilogue: coalesced, 8 threads per row
    int lane = t & 31;
    #pragma unroll
    for (int it = 0; it < 4; it++) {
        int row = (t >> 3) + it * 32;
        int c0 = (t & 7) * 16;
        int g = row0 + row;
        float elp = 0.f;
        if (g < Nn) {
            float* hsrow = &g_hs[((size_t)r * Nn + g) * 128];
            #pragma unroll
            for (int j = 0; j < 4; j++) {
                int c = c0 + j * 4;
                float4 v = *(float4*)&s->C[row * LDC + c];
                v.x += s->v0[c]; v.y += s->v0[c + 1]; v.z += s->v0[c + 2]; v.w += s->v0[c + 3];
                elp += v.x * s->v1[c] + v.y * s->v1[c + 1] + v.z * s->v1[c + 2] + v.w * s->v1[c + 3];
                *(float4*)&hsrow[c] = v;
            }
        }
        float sv = elp + __shfl_xor_sync(0xffffffffu, elp, 1);
        int base = lane & ~7;
        float e0 = __shfl_sync(0xffffffffu, sv, base + 0);
        float e1 = __shfl_sync(0xffffffffu, sv, base + 2);
        float e2 = __shfl_sync(0xffffffffu, sv, base + 4);
        float e3 = __shfl_sync(0xffffffffu, sv, base + 6);
        if ((lane & 7) == 0 && g < Nn)
            *(float4*)&g_el[((size_t)r * Nn + g) * 4] = make_float4(e0, e1, e2, e3);
    }
}

// ---------------- GEMM2 (wmma): wsum[r] += sum_n tanh(elu(rst+bg)@W1 + b1) . W2 ----------------
__global__ __launch_bounds__(256)
void k_gemm2_tc(const float* __restrict__ bias_g, const float* __restrict__ b1,
                const float* __restrict__ W2)
{
    extern __shared__ char smraw[];
    SmemG* s = (SmemG*)smraw;
    int t = threadIdx.x;
    int r = blockIdx.y;
    int row0 = blockIdx.x * 128;

    if (t < 128) {
        s->v0[t] = bias_g[r * 128 + t];
        s->v1[t] = b1[t];
        s->v2[t] = W2[t];
    }
    load_B_async(s, g_W1hi, g_W1lo, t);
    __syncthreads();   // v0 must be visible before A-tile build below

    const float* Xr = &g_rst[(size_t)r * Nn * 128];
    #pragma unroll
    for (int i = 0; i < 16; i++) {
        int e = i * 256 + t;
        int row = e >> 5, c4 = e & 31;
        int g = row0 + row;
        float4 v = make_float4(0.f, 0.f, 0.f, 0.f);
        if (g < Nn) {
            float4 x = *(const float4*)&Xr[(size_t)g * 128 + c4 * 4];
            int c = c4 * 4;
            x.x += s->v0[c]; x.y += s->v0[c + 1]; x.z += s->v0[c + 2]; x.w += s->v0[c + 3];
            v.x = x.x > 0.f ? x.x : expm1f(x.x);
            v.y = x.y > 0.f ? x.y : expm1f(x.y);
            v.z = x.z > 0.f ? x.z : expm1f(x.z);
            v.w = x.w > 0.f ? x.w : expm1f(x.w);
        }
        split_store4(s, row, c4, v);
    }
    cp_wait();
    __syncthreads();

    mma_main(s, t);
    __syncthreads();

    int lane = t & 31, w = t >> 5;
    float sp = 0.f;
    #pragma unroll
    for (int it = 0; it < 4; it++) {
        int row = (t >> 3) + it * 32;
        int c0 = (t & 7) * 16;
        int g = row0 + row;
        if (g < Nn) {
            #pragma unroll
            for (int j = 0; j < 4; j++) {
                int c = c0 + j * 4;
                float4 v = *(float4*)&s->C[row * LDC + c];
                sp += tanhf(v.x + s->v1[c])     * s->v2[c];
                sp += tanhf(v.y + s->v1[c + 1]) * s->v2[c + 1];
                sp += tanhf(v.z + s->v1[c + 2]) * s->v2[c + 2];
                sp += tanhf(v.w + s->v1[c + 3]) * s->v2[c + 3];
            }
        }
    }
    #pragma unroll
    for (int off = 16; off; off >>= 1) sp += __shfl_down_sync(0xffffffffu, sp, off);
    if (lane == 0) s->red[w] = sp;
    __syncthreads();
    if (t == 0) {
        float acc = 0.f;
        #pragma unroll
        for (int i = 0; i < 8; i++) acc += s->red[i];
        atomicAdd(&g_wsum[r], acc);
    }
}

// ---------------- er = dst_feat @ Q + qb (warp per n, all 3 relations) ----------------
__global__ void k_er(const float* __restrict__ dst_feat)
{
    __shared__ float sQ[Rr * 512];
    __shared__ float sqb[12];
    int t = threadIdx.x;
    for (int i = t; i < Rr * 512; i += 256) sQ[i] = g_Qt[i];
    if (t < 12) sqb[t] = g_qb[t];
    __syncthreads();
    int wid = t >> 5, lane = t & 31;
    int n = blockIdx.x * 8 + wid;
    if (n >= Nn) return;
    float4 x = *(const float4*)&dst_feat[(size_t)n * 128 + lane * 4];
    float p[12];
    #pragma unroll
    for (int i = 0; i < 12; i++) {
        float4 q = *(const float4*)&sQ[i * 128 + lane * 4];
        p[i] = x.x * q.x + x.y * q.y + x.z * q.z + x.w * q.w;
    }
    #pragma unroll
    for (int i = 0; i < 12; i++)
        #pragma unroll
        for (int off = 16; off; off >>= 1)
            p[i] += __shfl_down_sync(0xffffffffu, p[i], off);
    if (lane == 0) {
        #pragma unroll
        for (int i = 0; i < 12; i++) {
            int r = i >> 2, h = i & 3;
            g_er[((size_t)r * Nn + n) * 4 + h] = p[i] + sqb[i];
        }
    }
}

// ---------------- edge pass A: ex = exp(lrelu(el[s]+er[d])); segment sum ----------------
__global__ void k_edgeA(const int* __restrict__ sidx, const int* __restrict__ didx)
{
    int i = blockIdx.x * 256 + threadIdx.x;
    if (i >= Rr * Ee) return;
    int r = i / Ee;
    int s = sidx[i], d = didx[i];
    float4 el = *(const float4*)&g_el[((size_t)r * Nn + s) * 4];
    float4 er = *(const float4*)&g_er[((size_t)r * Nn + d) * 4];
    float4 ex;
    ex.x = expf(lrelu(el.x + er.x));
    ex.y = expf(lrelu(el.y + er.y));
    ex.z = expf(lrelu(el.z + er.z));
    ex.w = expf(lrelu(el.w + er.w));
    *(float4*)&g_e[(size_t)i * 4] = ex;
    float* sp = &g_ssum[((size_t)r * Nn + d) * 4];
    atomicAdd(sp + 0, ex.x);
    atomicAdd(sp + 1, ex.y);
    atomicAdd(sp + 2, ex.z);
    atomicAdd(sp + 3, ex.w);
}

// ---------------- edge pass 3: rst[d] += alpha * hs[s]  (warp per edge) ----------------
__global__ void k_edge3(const int* __restrict__ sidx, const int* __restrict__ didx)
{
    int w = (blockIdx.x * 256 + threadIdx.x) >> 5;
    int lane = threadIdx.x & 31;
    if (w >= Rr * Ee) return;
    int r = w / Ee;
    int s = sidx[w], d = didx[w];
    int h = lane >> 3;
    float ex = g_e[(size_t)w * 4 + h];
    float ss = g_ssum[((size_t)r * Nn + d) * 4 + h];
    float alpha = ex / (ss + 1e-9f);
    float4 hv = *(const float4*)&g_hs[((size_t)r * Nn + s) * 128 + lane * 4];
    float vx = hv.x * alpha, vy = hv.y * alpha, vz = hv.z * alpha, vw = hv.w * alpha;
    float* dst = &g_rst[((size_t)r * Nn + d) * 128 + lane * 4];
    asm volatile("red.global.add.v4.f32 [%0], {%1,%2,%3,%4};"
                 :: "l"(dst), "f"(vx), "f"(vy), "f"(vz), "f"(vw) : "memory");
}

// ---------------- softmax over relations ----------------
__global__ void k_soft(float* __restrict__ out)
{
    if (threadIdx.x == 0) {
        float v0 = g_wsum[0] / (float)Nn, v1 = g_wsum[1] / (float)Nn, v2 = g_wsum[2] / (float)Nn;
        float m = fmaxf(v0, fmaxf(v1, v2));
        float e0 = expf(v0 - m), e1 = expf(v1 - m), e2 = expf(v2 - m);
        float s = e0 + e1 + e2;
        g_a[0] = e0 / s; g_a[1] = e1 / s; g_a[2] = e2 / s;
        out[(size_t)Nn * 128 + 0] = e0 / s;
        out[(size_t)Nn * 128 + 1] = e1 / s;
        out[(size_t)Nn * 128 + 2] = e2 / s;
    }
}

// ---------------- z = sum_r a[r] * elu(rst_r + bias_g_r) ----------------
__global__ void k_final(float* __restrict__ out, const float* __restrict__ bias_g)
{
    int i = blockIdx.x * 256 + threadIdx.x;
    if (i >= Nn * 32) return;
    int j4 = i & 31;
    float a0 = g_a[0], a1 = g_a[1], a2 = g_a[2];
    float4 z = make_float4(0.f, 0.f, 0.f, 0.f);
    #pragma unroll
    for (int r = 0; r < 3; r++) {
        float ar = (r == 0) ? a0 : (r == 1) ? a1 : a2;
        float4 v = *(const float4*)&g_rst[((size_t)r * Nn * 32 + i) * 4];
        float4 b = *(const float4*)&bias_g[r * 128 + j4 * 4];
        v.x += b.x; v.y += b.y; v.z += b.z; v.w += b.w;
        v.x = v.x > 0.f ? v.x : expm1f(v.x);
        v.y = v.y > 0.f ? v.y : expm1f(v.y);
        v.z = v.z > 0.f ? v.z : expm1f(v.z);
        v.w = v.w > 0.f ? v.w : expm1f(v.w);
        z.x += ar * v.x; z.y += ar * v.y; z.z += ar * v.z; z.w += ar * v.w;
    }
    *(float4*)&out[(size_t)i * 4] = z;
}

// ---------------- launch ----------------
extern "C" void kernel_launch(void* const* d_in, const int* in_sizes, int n_in,
                              void* d_out, int out_size)
{
    const float* dst_feat  = (const float*)d_in[0];
    const float* src_feats = (const float*)d_in[1];
    const int*   src_idx   = (const int*)d_in[2];
    const int*   dst_idx   = (const int*)d_in[3];
    const float* Wt_dst    = (const float*)d_in[4];
    const float* bt_dst    = (const float*)d_in[5];
    const float* Wt_src    = (const float*)d_in[6];
    const float* bt_src    = (const float*)d_in[7];
    const float* Wg        = (const float*)d_in[8];
    const float* attn_l    = (const float*)d_in[9];
    const float* attn_r    = (const float*)d_in[10];
    const float* bias_g    = (const float*)d_in[11];
    const float* W1        = (const float*)d_in[12];
    const float* b1        = (const float*)d_in[13];
    const float* W2        = (const float*)d_in[14];
    float* out = (float*)d_out;

    static bool attr_set = false;
    if (!attr_set) {
        cudaFuncSetAttribute(k_gemm1_tc, cudaFuncAttributeMaxDynamicSharedMemorySize, SM_TOTAL);
        cudaFuncSetAttribute(k_gemm2_tc, cudaFuncAttributeMaxDynamicSharedMemorySize, SM_TOTAL);
        attr_set = true;
    }

    k_compose<<<dim3(129, Rr), 256>>>(Wt_dst, bt_dst, Wt_src, bt_src, Wg);
    k_prepW1<<<64, 256>>>(W1);
    k_attnproj<<<Rr, 128>>>(attn_r);
    k_init<<<(Rr * Nn * 32 + 255) / 256, 256>>>();

    dim3 gg((Nn + 127) / 128, Rr);
    k_gemm1_tc<<<gg, 256, SM_TOTAL>>>(src_feats, attn_l);

    k_er<<<(Nn + 7) / 8, 256>>>(dst_feat);

    k_edgeA<<<(Rr * Ee + 255) / 256, 256>>>(src_idx, dst_idx);
    k_edge3<<<(Rr * Ee + 7) / 8, 256>>>(src_idx, dst_idx);

    k_gemm2_tc<<<gg, 256, SM_TOTAL>>>(bias_g, b1, W2);

    k_soft<<<1, 32>>>(out);
    k_final<<<(Nn * 32 + 255) / 256, 256>>>(out, bias_g);
}

// round 11
// speedup vs baseline: 1.5631x; 1.1974x over previous
#include <cuda_runtime.h>
#include <cuda_bf16.h>
#include <mma.h>
#include <cstdint>

using namespace nvcuda;

#define Nn 100000
#define Rr 3
#define Ee 320000
#define HDIM 128
#define NT (Rr * Nn)          // 300000 segment nodes
#define NBLK ((NT + 1023) / 1024)

// ---------------- scratch (device globals) ----------------
__device__ float g_B[Rr * 128 * 128];               // Wt_dst @ Wg (fp32, for attnproj)
__device__ float g_bA[Rr * 128];                    // bt_src @ Wg
__device__ float g_bB[Rr * 128];                    // bt_dst @ Wg
__device__ float g_Qt[Rr * 4 * 128];                // er projection [r][h][f]
__device__ float g_qb[Rr * 4];
__device__ __nv_bfloat16 g_Whi[Rr * 128 * 128];     // (Wt_src@Wg)^T bf16 hi  [n][k]
__device__ __nv_bfloat16 g_Wlo[Rr * 128 * 128];     // lo
__device__ __nv_bfloat16 g_W1hi[128 * 128];         // W1^T bf16 hi [n][k]
__device__ __nv_bfloat16 g_W1lo[128 * 128];
__device__ float g_hs[Rr * Nn * HDIM];              // projected src features (biased)
__device__ float g_el[Rr * Nn * 4];
__device__ float g_er[Rr * Nn * 4];
__device__ float g_rst[Rr * Nn * HDIM];             // aggregation (written once by k_agg)
__device__ float g_wsum[Rr];
__device__ float g_a[Rr];
// CSR scratch
__device__ int g_deg[NT];
__device__ int g_off[NT + 1];
__device__ int g_cur[NT];
__device__ int g_bsum[1024];
__device__ int g_csr_src[Rr * Ee];

__device__ __forceinline__ float lrelu(float x) { return x > 0.f ? x : 0.2f * x; }

__device__ __forceinline__ uint32_t smem_u32(const void* p) {
    uint32_t a;
    asm("{ .reg .u64 t; cvta.to.shared.u64 t, %1; cvt.u32.u64 %0, t; }" : "=r"(a) : "l"(p));
    return a;
}
__device__ __forceinline__ void cp16(uint32_t dst, const void* src) {
    asm volatile("cp.async.cg.shared.global [%0], [%1], 16;" :: "r"(dst), "l"(src) : "memory");
}
__device__ __forceinline__ void cp_commit() {
    asm volatile("cp.async.commit_group;" ::: "memory");
}
__device__ __forceinline__ void cp_wait() {
    asm volatile("cp.async.wait_group 0;" ::: "memory");
}

// ---------------- SMEM overlay for GEMM kernels ----------------
#define LDA 136   // bf16 elements per A/B smem row (conflict-free ldmatrix)
#define LDC 132   // f32 elements per C smem row
struct SmemG {
    union {
        struct {
            __nv_bfloat16 Ahi[128 * LDA];
            __nv_bfloat16 Alo[128 * LDA];
        } a;
        float C[128 * LDC];   // aliases A: safe after post-MMA barrier
    } u;
    __nv_bfloat16 Bh[128 * LDA];
    __nv_bfloat16 Bl[128 * LDA];
    float v0[128], v1[128], v2[128];
    float red[16];
};
#define SM_TOTAL ((int)sizeof(SmemG))

// split fp32 -> hi/lo bf16 pair, store 4 values to A tiles
__device__ __forceinline__ void split_store4(SmemG* s, int row, int c4, float4 v) {
    __nv_bfloat16 h0 = __float2bfloat16(v.x), h1 = __float2bfloat16(v.y);
    __nv_bfloat16 h2 = __float2bfloat16(v.z), h3 = __float2bfloat16(v.w);
    __nv_bfloat16 l0 = __float2bfloat16(v.x - __bfloat162float(h0));
    __nv_bfloat16 l1 = __float2bfloat16(v.y - __bfloat162float(h1));
    __nv_bfloat16 l2 = __float2bfloat16(v.z - __bfloat162float(h2));
    __nv_bfloat16 l3 = __float2bfloat16(v.w - __bfloat162float(h3));
    __nv_bfloat162 hA = __halves2bfloat162(h0, h1), hB = __halves2bfloat162(h2, h3);
    __nv_bfloat162 lA = __halves2bfloat162(l0, l1), lB = __halves2bfloat162(l2, l3);
    int off = row * LDA + c4 * 4;
    *(uint2*)&s->u.a.Ahi[off] = make_uint2(*(uint32_t*)&hA, *(uint32_t*)&hB);
    *(uint2*)&s->u.a.Alo[off] = make_uint2(*(uint32_t*)&lA, *(uint32_t*)&lB);
}

// async loads for the 128x128 weight tile (hi+lo): 2048 chunks of 8 bf16 (512 thr)
__device__ __forceinline__ void load_B_async(SmemG* s, const __nv_bfloat16* Bhi,
                                             const __nv_bfloat16* Blo, int t) {
    uint32_t bh = smem_u32(s->Bh), bl = smem_u32(s->Bl);
    #pragma unroll
    for (int i = 0; i < 4; i++) {
        int e = i * 512 + t;
        int n = e >> 4, k8 = e & 15;
        uint32_t so = (uint32_t)(n * LDA + k8 * 8) * 2;
        cp16(bh + so, Bhi + (size_t)n * 128 + k8 * 8);
        cp16(bl + so, Blo + (size_t)n * 128 + k8 * 8);
    }
    cp_commit();
}

// 3-pass split-bf16 MMA mainloop; 16 warps: (wm 0..7) x (wn 0..1); C staged in smem
__device__ __forceinline__ void mma_main(SmemG* s, int t) {
    int w = t >> 5;
    int wm = w >> 1, wn = w & 1;
    wmma::fragment<wmma::accumulator, 16, 16, 16, float> acc[4];
    #pragma unroll
    for (int n = 0; n < 4; n++) wmma::fill_fragment(acc[n], 0.f);

    #pragma unroll
    for (int pass = 0; pass < 3; pass++) {
        const __nv_bfloat16* As = (pass == 2) ? s->u.a.Alo : s->u.a.Ahi;
        const __nv_bfloat16* Bs = (pass == 1) ? s->Bl : s->Bh;
        #pragma unroll
        for (int k = 0; k < 8; k++) {
            wmma::fragment<wmma::matrix_a, 16, 16, 16, __nv_bfloat16, wmma::row_major> af;
            wmma::load_matrix_sync(af, As + wm * 16 * LDA + k * 16, LDA);
            #pragma unroll
            for (int n = 0; n < 4; n++) {
                wmma::fragment<wmma::matrix_b, 16, 16, 16, __nv_bfloat16, wmma::col_major> bf;
                wmma::load_matrix_sync(bf, Bs + (wn * 64 + n * 16) * LDA + k * 16, LDA);
                wmma::mma_sync(acc[n], af, bf, acc[n]);
            }
        }
    }
    __syncthreads();   // all A/B reads done -> C may overwrite A region
    #pragma unroll
    for (int n = 0; n < 4; n++)
        wmma::store_matrix_sync(s->u.C + wm * 16 * LDC + wn * 64 + n * 16, acc[n], LDC,
                                wmma::mem_row_major);
}

// ---------------- K0: composed weights ----------------
__global__ void k_compose(const float* __restrict__ Wt_dst, const float* __restrict__ bt_dst,
                          const float* __restrict__ Wt_src, const float* __restrict__ bt_src,
                          const float* __restrict__ Wg)
{
    int r = blockIdx.y;
    int o = blockIdx.x * 256 + threadIdx.x;
    if (o >= 2 * 16384 + 2 * 128) return;
    const float* WgR = Wg + r * 16384;
    if (o < 32768) {
        int which = o >> 14;
        int idx = o & 16383;
        int f = idx >> 7, j = idx & 127;
        const float* row = which ? (Wt_dst + f * 128) : (Wt_src + r * 16384 + f * 128);
        float s = 0.f;
        #pragma unroll 8
        for (int k = 0; k < 128; k++) s += row[k] * WgR[k * 128 + j];
        if (which) {
            g_B[r * 16384 + idx] = s;
        } else {
            __nv_bfloat16 h = __float2bfloat16(s);
            __nv_bfloat16 l = __float2bfloat16(s - __bfloat162float(h));
            g_Whi[r * 16384 + j * 128 + f] = h;   // transposed [n=j][k=f]
            g_Wlo[r * 16384 + j * 128 + f] = l;
        }
    } else {
        int o2 = o - 32768;
        int which = o2 >> 7;
        int j = o2 & 127;
        const float* bv = which ? bt_dst : (bt_src + r * 128);
        float s = 0.f;
        #pragma unroll 8
        for (int k = 0; k < 128; k++) s += bv[k] * WgR[k * 128 + j];
        if (which) g_bB[r * 128 + j] = s;
        else       g_bA[r * 128 + j] = s;
    }
}

// ---------------- K0b: W1^T bf16 split ----------------
__global__ void k_prepW1(const float* __restrict__ W1)
{
    int idx = blockIdx.x * 256 + threadIdx.x;
    if (idx >= 16384) return;
    int n = idx >> 7, k = idx & 127;
    float w = W1[k * 128 + n];
    __nv_bfloat16 h = __float2bfloat16(w);
    __nv_bfloat16 l = __float2bfloat16(w - __bfloat162float(h));
    g_W1hi[n * 128 + k] = h;
    g_W1lo[n * 128 + k] = l;
}

// ---------------- K0c: er projection Q = B . attn_r ----------------
__global__ void k_attnproj(const float* __restrict__ attn_r_)
{
    int r = blockIdx.x;
    int f = threadIdx.x;
    #pragma unroll
    for (int h = 0; h < 4; h++) {
        float s = 0.f;
        #pragma unroll 8
        for (int d = 0; d < 32; d++)
            s += g_B[r * 16384 + f * 128 + h * 32 + d] * attn_r_[r * 128 + h * 32 + d];
        g_Qt[r * 512 + h * 128 + f] = s;
    }
    if (f < 4) {
        int h = f;
        float s = 0.f;
        for (int d = 0; d < 32; d++)
            s += g_bB[r * 128 + h * 32 + d] * attn_r_[r * 128 + h * 32 + d];
        g_qb[r * 4 + h] = s;
    }
}

// ---------------- init: zero degree counters + wsum ----------------
__global__ void k_init()
{
    int i = blockIdx.x * 256 + threadIdx.x;
    if (i * 4 < NT) {
        int4 z = make_int4(0, 0, 0, 0);
        *(int4*)&g_deg[i * 4] = z;
    }
    if (i < Rr) g_wsum[i] = 0.f;
}

// ---------------- CSR build ----------------
__global__ void k_hist(const int* __restrict__ didx)
{
    int i = blockIdx.x * 256 + threadIdx.x;
    if (i >= Rr * Ee) return;
    int r = i / Ee;
    atomicAdd(&g_deg[r * Nn + didx[i]], 1);
}

__global__ void k_scan1()
{
    __shared__ int sh[1024];
    int t = threadIdx.x;
    int i = blockIdx.x * 1024 + t;
    int v = (i < NT) ? g_deg[i] : 0;
    sh[t] = v;
    __syncthreads();
    #pragma unroll
    for (int off = 1; off < 1024; off <<= 1) {
        int y = (t >= off) ? sh[t - off] : 0;
        __syncthreads();
        sh[t] += y;
        __syncthreads();
    }
    if (i < NT) g_off[i] = sh[t] - v;
    if (t == 1023) g_bsum[blockIdx.x] = sh[1023];
}

__global__ void k_scan2()
{
    __shared__ int sh[512];
    int t = threadIdx.x;
    int v = (t < NBLK) ? g_bsum[t] : 0;
    sh[t] = v;
    __syncthreads();
    #pragma unroll
    for (int off = 1; off < 512; off <<= 1) {
        int y = (t >= off) ? sh[t - off] : 0;
        __syncthreads();
        sh[t] += y;
        __syncthreads();
    }
    if (t < NBLK) g_bsum[t] = sh[t] - v;
}

__global__ void k_scan3()
{
    int i = blockIdx.x * 256 + threadIdx.x;
    if (i < NT) {
        int off = g_off[i] + g_bsum[i >> 10];
        g_off[i] = off;
        g_cur[i] = off;
    }
    if (i == 0) g_off[NT] = Rr * Ee;
}

__global__ void k_scatter(const int* __restrict__ sidx, const int* __restrict__ didx)
{
    int i = blockIdx.x * 256 + threadIdx.x;
    if (i >= Rr * Ee) return;
    int r = i / Ee;
    int node = r * Nn + didx[i];
    int pos = atomicAdd(&g_cur[node], 1);
    g_csr_src[pos] = sidx[i];
}

// ---------------- GEMM1 (wmma, 512 thr): hs = X @ A + bA, fused el ----------------
__global__ __launch_bounds__(512)
void k_gemm1_tc(const float* __restrict__ src_feats, const float* __restrict__ attn_l_)
{
    extern __shared__ char smraw[];
    SmemG* s = (SmemG*)smraw;
    int t = threadIdx.x;
    int r = blockIdx.y;
    int row0 = blockIdx.x * 128;

    if (t < 128) {
        s->v0[t] = g_bA[r * 128 + t];
        s->v1[t] = attn_l_[r * 128 + t];
    }
    load_B_async(s, g_Whi + r * 16384, g_Wlo + r * 16384, t);

    const float* X = src_feats + (size_t)r * Nn * 128;
    #pragma unroll
    for (int i = 0; i < 8; i++) {
        int e = i * 512 + t;
        int row = e >> 5, c4 = e & 31;
        int g = row0 + row;
        float4 v = (g < Nn) ? *(const float4*)&X[(size_t)g * 128 + c4 * 4]
                            : make_float4(0.f, 0.f, 0.f, 0.f);
        split_store4(s, row, c4, v);
    }
    cp_wait();
    __syncthreads();

    mma_main(s, t);
    __syncthreads();

    // epilogue: 8 threads per row, 2 row-iters
    int lane = t & 31;
    #pragma unroll
    for (int it = 0; it < 2; it++) {
        int row = (t >> 3) + it * 64;
        int c0 = (t & 7) * 16;
        int g = row0 + row;
        float elp = 0.f;
        if (g < Nn) {
            float* hsrow = &g_hs[((size_t)r * Nn + g) * 128];
            #pragma unroll
            for (int j = 0; j < 4; j++) {
                int c = c0 + j * 4;
                float4 v = *(float4*)&s->u.C[row * LDC + c];
                v.x += s->v0[c]; v.y += s->v0[c + 1]; v.z += s->v0[c + 2]; v.w += s->v0[c + 3];
                elp += v.x * s->v1[c] + v.y * s->v1[c + 1] + v.z * s->v1[c + 2] + v.w * s->v1[c + 3];
                *(float4*)&hsrow[c] = v;
            }
        }
        float sv = elp + __shfl_xor_sync(0xffffffffu, elp, 1);
        int base = lane & ~7;
        float e0 = __shfl_sync(0xffffffffu, sv, base + 0);
        float e1 = __shfl_sync(0xffffffffu, sv, base + 2);
        float e2 = __shfl_sync(0xffffffffu, sv, base + 4);
        float e3 = __shfl_sync(0xffffffffu, sv, base + 6);
        if ((lane & 7) == 0 && g < Nn)
            *(float4*)&g_el[((size_t)r * Nn + g) * 4] = make_float4(e0, e1, e2, e3);
    }
}

// ---------------- GEMM2 (wmma, 512 thr): wsum[r] += sum_n tanh(elu(rst+bg)@W1+b1).W2 ----------------
__global__ __launch_bounds__(512)
void k_gemm2_tc(const float* __restrict__ bias_g, const float* __restrict__ b1,
                const float* __restrict__ W2)
{
    extern __shared__ char smraw[];
    SmemG* s = (SmemG*)smraw;
    int t = threadIdx.x;
    int r = blockIdx.y;
    int row0 = blockIdx.x * 128;

    if (t < 128) {
        s->v0[t] = bias_g[r * 128 + t];
        s->v1[t] = b1[t];
        s->v2[t] = W2[t];
    }
    load_B_async(s, g_W1hi, g_W1lo, t);
    __syncthreads();   // v0 visible before A-tile build

    const float* Xr = &g_rst[(size_t)r * Nn * 128];
    #pragma unroll
    for (int i = 0; i < 8; i++) {
        int e = i * 512 + t;
        int row = e >> 5, c4 = e & 31;
        int g = row0 + row;
        float4 v = make_float4(0.f, 0.f, 0.f, 0.f);
        if (g < Nn) {
            float4 x = *(const float4*)&Xr[(size_t)g * 128 + c4 * 4];
            int c = c4 * 4;
            x.x += s->v0[c]; x.y += s->v0[c + 1]; x.z += s->v0[c + 2]; x.w += s->v0[c + 3];
            v.x = x.x > 0.f ? x.x : expm1f(x.x);
            v.y = x.y > 0.f ? x.y : expm1f(x.y);
            v.z = x.z > 0.f ? x.z : expm1f(x.z);
            v.w = x.w > 0.f ? x.w : expm1f(x.w);
        }
        split_store4(s, row, c4, v);
    }
    cp_wait();
    __syncthreads();

    mma_main(s, t);
    __syncthreads();

    int lane = t & 31, w = t >> 5;
    float sp = 0.f;
    #pragma unroll
    for (int it = 0; it < 2; it++) {
        int row = (t >> 3) + it * 64;
        int c0 = (t & 7) * 16;
        int g = row0 + row;
        if (g < Nn) {
            #pragma unroll
            for (int j = 0; j < 4; j++) {
                int c = c0 + j * 4;
                float4 v = *(float4*)&s->u.C[row * LDC + c];
                sp += tanhf(v.x + s->v1[c])     * s->v2[c];
                sp += tanhf(v.y + s->v1[c + 1]) * s->v2[c + 1];
                sp += tanhf(v.z + s->v1[c + 2]) * s->v2[c + 2];
                sp += tanhf(v.w + s->v1[c + 3]) * s->v2[c + 3];
            }
        }
    }
    #pragma unroll
    for (int off = 16; off; off >>= 1) sp += __shfl_down_sync(0xffffffffu, sp, off);
    if (lane == 0) s->red[w] = sp;
    __syncthreads();
    if (t == 0) {
        float acc = 0.f;
        #pragma unroll
        for (int i = 0; i < 16; i++) acc += s->red[i];
        atomicAdd(&g_wsum[r], acc);
    }
}

// ---------------- er = dst_feat @ Q + qb (warp per n, all 3 relations) ----------------
__global__ void k_er(const float* __restrict__ dst_feat)
{
    __shared__ float sQ[Rr * 512];
    __shared__ float sqb[12];
    int t = threadIdx.x;
    for (int i = t; i < Rr * 512; i += 256) sQ[i] = g_Qt[i];
    if (t < 12) sqb[t] = g_qb[t];
    __syncthreads();
    int wid = t >> 5, lane = t & 31;
    int n = blockIdx.x * 8 + wid;
    if (n >= Nn) return;
    float4 x = *(const float4*)&dst_feat[(size_t)n * 128 + lane * 4];
    float p[12];
    #pragma unroll
    for (int i = 0; i < 12; i++) {
        float4 q = *(const float4*)&sQ[i * 128 + lane * 4];
        p[i] = x.x * q.x + x.y * q.y + x.z * q.z + x.w * q.w;
    }
    #pragma unroll
    for (int i = 0; i < 12; i++)
        #pragma unroll
        for (int off = 16; off; off >>= 1)
            p[i] += __shfl_down_sync(0xffffffffu, p[i], off);
    if (lane == 0) {
        #pragma unroll
        for (int i = 0; i < 12; i++) {
            int r = i >> 2, h = i & 3;
            g_er[((size_t)r * Nn + n) * 4 + h] = p[i] + sqb[i];
        }
    }
}

// ---------------- aggregation: warp per (r,dst) node via CSR ----------------
__global__ __launch_bounds__(256)
void k_agg()
{
    __shared__ float exbuf[8][64][4];
    int gw = (blockIdx.x * 256 + threadIdx.x) >> 5;
    int lane = threadIdx.x & 31;
    int wl = (threadIdx.x >> 5);
    if (gw >= NT) return;
    int r = gw / Nn;
    int beg = g_off[gw], end = g_off[gw + 1];

    float4 er = *(const float4*)&g_er[(size_t)gw * 4];

    float s0 = 0.f, s1 = 0.f, s2 = 0.f, s3 = 0.f;
    for (int e = beg + lane; e < end; e += 32) {
        int sn = g_csr_src[e];
        float4 el = *(const float4*)&g_el[((size_t)r * Nn + sn) * 4];
        float ex0 = expf(lrelu(el.x + er.x));
        float ex1 = expf(lrelu(el.y + er.y));
        float ex2 = expf(lrelu(el.z + er.z));
        float ex3 = expf(lrelu(el.w + er.w));
        int j = e - beg;
        if (j < 64) {
            exbuf[wl][j][0] = ex0; exbuf[wl][j][1] = ex1;
            exbuf[wl][j][2] = ex2; exbuf[wl][j][3] = ex3;
        }
        s0 += ex0; s1 += ex1; s2 += ex2; s3 += ex3;
    }
    #pragma unroll
    for (int off = 16; off; off >>= 1) {
        s0 += __shfl_xor_sync(0xffffffffu, s0, off);
        s1 += __shfl_xor_sync(0xffffffffu, s1, off);
        s2 += __shfl_xor_sync(0xffffffffu, s2, off);
        s3 += __shfl_xor_sync(0xffffffffu, s3, off);
    }
    __syncwarp();

    int h = lane >> 3;
    float ssh = (h == 0 ? s0 : h == 1 ? s1 : h == 2 ? s2 : s3) + 1e-9f;
    float erh = (h == 0 ? er.x : h == 1 ? er.y : h == 2 ? er.z : er.w);

    float4 acc = make_float4(0.f, 0.f, 0.f, 0.f);
    int deg = end - beg;
    for (int j = 0; j < deg; j++) {
        int sn = g_csr_src[beg + j];
        float exh;
        if (j < 64) {
            exh = exbuf[wl][j][h];
        } else {
            float elh = g_el[((size_t)r * Nn + sn) * 4 + h];
            exh = expf(lrelu(elh + erh));
        }
        float a = exh / ssh;
        float4 hv = *(const float4*)&g_hs[((size_t)r * Nn + sn) * 128 + lane * 4];
        acc.x += a * hv.x; acc.y += a * hv.y; acc.z += a * hv.z; acc.w += a * hv.w;
    }
    *(float4*)&g_rst[(size_t)gw * 128 + lane * 4] = acc;
}

// ---------------- softmax over relations ----------------
__global__ void k_soft(float* __restrict__ out)
{
    if (threadIdx.x == 0) {
        float v0 = g_wsum[0] / (float)Nn, v1 = g_wsum[1] / (float)Nn, v2 = g_wsum[2] / (float)Nn;
        float m = fmaxf(v0, fmaxf(v1, v2));
        float e0 = expf(v0 - m), e1 = expf(v1 - m), e2 = expf(v2 - m);
        float s = e0 + e1 + e2;
        g_a[0] = e0 / s; g_a[1] = e1 / s; g_a[2] = e2 / s;
        out[(size_t)Nn * 128 + 0] = e0 / s;
        out[(size_t)Nn * 128 + 1] = e1 / s;
        out[(size_t)Nn * 128 + 2] = e2 / s;
    }
}

// ---------------- z = sum_r a[r] * elu(rst_r + bias_g_r) ----------------
__global__ void k_final(float* __restrict__ out, const float* __restrict__ bias_g)
{
    int i = blockIdx.x * 256 + threadIdx.x;
    if (i >= Nn * 32) return;
    int j4 = i & 31;
    float a0 = g_a[0], a1 = g_a[1], a2 = g_a[2];
    float4 z = make_float4(0.f, 0.f, 0.f, 0.f);
    #pragma unroll
    for (int r = 0; r < 3; r++) {
        float ar = (r == 0) ? a0 : (r == 1) ? a1 : a2;
        float4 v = *(const float4*)&g_rst[((size_t)r * Nn * 32 + i) * 4];
        float4 b = *(const float4*)&bias_g[r * 128 + j4 * 4];
        v.x += b.x; v.y += b.y; v.z += b.z; v.w += b.w;
        v.x = v.x > 0.f ? v.x : expm1f(v.x);
        v.y = v.y > 0.f ? v.y : expm1f(v.y);
        v.z = v.z > 0.f ? v.z : expm1f(v.z);
        v.w = v.w > 0.f ? v.w : expm1f(v.w);
        z.x += ar * v.x; z.y += ar * v.y; z.z += ar * v.z; z.w += ar * v.w;
    }
    *(float4*)&out[(size_t)i * 4] = z;
}

// ---------------- launch ----------------
extern "C" void kernel_launch(void* const* d_in, const int* in_sizes, int n_in,
                              void* d_out, int out_size)
{
    const float* dst_feat  = (const float*)d_in[0];
    const float* src_feats = (const float*)d_in[1];
    const int*   src_idx   = (const int*)d_in[2];
    const int*   dst_idx   = (const int*)d_in[3];
    const float* Wt_dst    = (const float*)d_in[4];
    const float* bt_dst    = (const float*)d_in[5];
    const float* Wt_src    = (const float*)d_in[6];
    const float* bt_src    = (const float*)d_in[7];
    const float* Wg        = (const float*)d_in[8];
    const float* attn_l    = (const float*)d_in[9];
    const float* attn_r    = (const float*)d_in[10];
    const float* bias_g    = (const float*)d_in[11];
    const float* W1        = (const float*)d_in[12];
    const float* b1        = (const float*)d_in[13];
    const float* W2        = (const float*)d_in[14];
    float* out = (float*)d_out;

    static bool attr_set = false;
    if (!attr_set) {
        cudaFuncSetAttribute(k_gemm1_tc, cudaFuncAttributeMaxDynamicSharedMemorySize, SM_TOTAL);
        cudaFuncSetAttribute(k_gemm2_tc, cudaFuncAttributeMaxDynamicSharedMemorySize, SM_TOTAL);
        attr_set = true;
    }

    k_compose<<<dim3(129, Rr), 256>>>(Wt_dst, bt_dst, Wt_src, bt_src, Wg);
    k_prepW1<<<64, 256>>>(W1);
    k_attnproj<<<Rr, 128>>>(attn_r);
    k_init<<<(NT / 4 + 255) / 256, 256>>>();

    // CSR build (independent of GEMM1)
    k_hist<<<(Rr * Ee + 255) / 256, 256>>>(dst_idx);
    k_scan1<<<NBLK, 1024>>>();
    k_scan2<<<1, 512>>>();
    k_scan3<<<(NT + 255) / 256, 256>>>();
    k_scatter<<<(Rr * Ee + 255) / 256, 256>>>(src_idx, dst_idx);

    dim3 gg((Nn + 127) / 128, Rr);
    k_gemm1_tc<<<gg, 512, SM_TOTAL>>>(src_feats, attn_l);

    k_er<<<(Nn + 7) / 8, 256>>>(dst_feat);

    k_agg<<<(NT * 32 + 255) / 256, 256>>>();

    k_gemm2_tc<<<gg, 512, SM_TOTAL>>>(bias_g, b1, W2);

    k_soft<<<1, 32>>>(out);
    k_final<<<(Nn * 32 + 255) / 256, 256>>>(out, bias_g);
}